// round 14
// baseline (speedup 1.0000x reference)
#include <cuda_runtime.h>
#include <cuda_bf16.h>
#include <cstdint>

// FSQ: q = round(4*tanh( W @ LayerNorm(x) )), folded into a single pass:
//   logit_n = rstd * (dot(x, gamma*W_n) - mu * s_n) + b_n
// R14: R=8 rows/warp with SCALAR dots (f32x2 proved half-rate: saves issue
// slots only, and its 128-reg bank blocks R>4). Halves W-LDS per row — the
// measured l1tex wall. Warp-private cp.async, NBUF=2, wait_group 1.

typedef unsigned long long u64;

// rintf(4*tanh(x)), fast-math-proof (fmaf/rcp.rn/sqrt.rn only).
__device__ __forceinline__ float tanh4_round(float x) {
    float ax = fabsf(x);
    float r;
    if (ax >= 1.5f) {
        r = 4.0f;   // 4*tanh(1.5)=3.6206 -> 4; monotone beyond
    } else {
        const float T2L = 2.8853900817779268f;   // 2*log2(e)
        float t = ax * T2L;
        float k = rintf(t);
        float f = t - k;
        float y = f * 0.6931471805599453f;
        float p = 1.9841269841e-4f;
        p = fmaf(p, y, 1.3888888888e-3f);
        p = fmaf(p, y, 8.3333333333e-3f);
        p = fmaf(p, y, 4.1666666667e-2f);
        p = fmaf(p, y, 1.6666666667e-1f);
        p = fmaf(p, y, 0.5f);
        p = fmaf(p, y, 1.0f);
        p = fmaf(p, y, 1.0f);
        float scale = __int_as_float(((int)k + 127) << 23);
        float e = p * scale;                     // exp(2*ax)
        float th = (e - 1.0f) * __frcp_rn(e + 1.0f);
        r = rintf(4.0f * th);
    }
    return copysignf(r, x);
}

static const int D       = 1024;
static const int F4      = 256;   // 16B chunks per row
static const int NL      = 8;
static const int WPAD    = 9;     // float4 entries per chunk (8 + 1 pad)
static const int R       = 8;     // rows per warp
static const int ROWS_PB = 64;    // 8 warps * 8 rows
static const int NSTAGE  = 8;     // stages of 32 chunks (512B/row)
static const int NBUF    = 2;     // double buffer (warp-private)

// dynamic smem layout (bytes)
static const int SW_BYTES = F4 * WPAD * 16;             // 36864
static const int SX_BYTES = 8 * NBUF * R * 32 * 16;     // 65536 (8 warps)
static const int ST_BYTES = ROWS_PB * 12 * 4;           // 3072
static const int SR_BYTES = 8 * 16 * 4;                 // 512
static const int SMEM_TOTAL = SW_BYTES + SX_BYTES + ST_BYTES + SR_BYTES + 64;

__global__ void __launch_bounds__(256, 2)
fsq_kernel(const float* __restrict__ x, const float* __restrict__ gamma,
           const float* __restrict__ beta, const float* __restrict__ W,
           float* __restrict__ out, int rows)
{
    extern __shared__ unsigned char smem_raw[];
    float4* sW = (float4*)smem_raw;                                // [F4*WPAD]
    float4* sX = (float4*)(smem_raw + SW_BYTES);                   // [8][NBUF][8][32]
    float (*sStats)[12] = (float(*)[12])(smem_raw + SW_BYTES + SX_BYTES);
    float (*sRed)[16]   = (float(*)[16])(smem_raw + SW_BYTES + SX_BYTES + ST_BYTES);
    float* sSB          = (float*)(smem_raw + SW_BYTES + SX_BYTES + ST_BYTES + SR_BYTES);

    const int tid  = threadIdx.x;
    const int lane = tid & 31;
    const int wid  = tid >> 5;

    int rowBase = blockIdx.x * ROWS_PB;
    if (rowBase > rows - ROWS_PB) rowBase = rows - ROWS_PB;  // safety (exact fit)
    if (rowBase < 0) rowBase = 0;

    // this warp's private region: NBUF stages x 8 rows x 32 chunks
    const uint32_t sx_u32 = (uint32_t)__cvta_generic_to_shared(sX)
                          + (uint32_t)wid * (NBUF * R * 32 * 16);
    const float4* x4 = (const float4*)x;
    const int myRow = rowBase + wid * R;

    // ---- warp-private cp.async stage issuer: stage s -> buffer (s & 1) ----
    auto issue_stage = [&](int s) {
        uint32_t dbase = sx_u32 + (uint32_t)(s & (NBUF - 1)) * (R * 32 * 16);
#pragma unroll
        for (int r = 0; r < R; r++) {
            const float4* src = x4 + (size_t)(myRow + r) * F4 + s * 32 + lane;
            uint32_t dst = dbase + (uint32_t)(r * 32 + lane) * 16;
            asm volatile("cp.async.cg.shared.global [%0], [%1], 16;"
                         :: "r"(dst), "l"(src) : "memory");
        }
        asm volatile("cp.async.commit_group;" ::: "memory");
    };

    // prologue: both buffers in flight before anything else
    issue_stage(0);
    issue_stage(1);

    // ---------------- prep: W' = gamma*W into smem; s_n, b_n ----------------
    float sP[NL], bP[NL];
#pragma unroll
    for (int n = 0; n < NL; n++) { sP[n] = 0.0f; bP[n] = 0.0f; }
    {
        const float4* g4 = (const float4*)gamma;  // [256]
        const float4* e4 = (const float4*)beta;
        const float4* W4 = (const float4*)W;      // [8][256]
        int i = tid;                              // 256 threads = 256 chunks
        float4 g = g4[i];
        float4 b = e4[i];
#pragma unroll
        for (int n = 0; n < NL; n++) {
            float4 w = W4[n * F4 + i];
            float4 p;
            p.x = g.x * w.x; p.y = g.y * w.y; p.z = g.z * w.z; p.w = g.w * w.w;
            sW[i * WPAD + n] = p;
            sP[n] += (p.x + p.y) + (p.z + p.w);
            bP[n] += (b.x * w.x + b.y * w.y) + (b.z * w.z + b.w * w.w);
        }
    }
#pragma unroll
    for (int o = 16; o; o >>= 1) {
#pragma unroll
        for (int n = 0; n < NL; n++) {
            sP[n] += __shfl_xor_sync(0xffffffffu, sP[n], o);
            bP[n] += __shfl_xor_sync(0xffffffffu, bP[n], o);
        }
    }
    if (lane == 0) {
#pragma unroll
        for (int n = 0; n < NL; n++) {
            sRed[wid][n]     = sP[n];
            sRed[wid][8 + n] = bP[n];
        }
    }
    __syncthreads();
    if (tid < 16) {
        float v = 0.0f;
#pragma unroll
        for (int w = 0; w < 8; w++) v += sRed[w][tid];
        sSB[tid] = v;
    }
    __syncthreads();   // sW/sSB visible; mainloop has no block barriers

    // ---------------- main: warp-private staged pipeline ----------------
    float dots[R][NL];                 // scalar accumulators (64 regs)
    float sum[R], ssq[R];              // scalar stats (16 regs)
#pragma unroll
    for (int r = 0; r < R; r++) {
        sum[r] = 0.0f; ssq[r] = 0.0f;
#pragma unroll
        for (int n = 0; n < NL; n++) dots[r][n] = 0.0f;
    }

#pragma unroll
    for (int s = 0; s < NSTAGE; s++) {
        // this warp's stage s landed (1 newer group may be pending)
        asm volatile("cp.async.wait_group 1;" ::: "memory");
        __syncwarp();

        // consume stage s: all 8 rows resident, W streamed per level
        const float4* xbuf = (const float4*)(smem_raw + SW_BYTES)
            + (size_t)wid * (NBUF * R * 32)
            + (s & (NBUF - 1)) * (R * 32) + lane;
        float4 c[R];
#pragma unroll
        for (int r = 0; r < R; r++) c[r] = xbuf[r * 32];

#pragma unroll
        for (int r = 0; r < R; r++) {
            sum[r] += (c[r].x + c[r].y) + (c[r].z + c[r].w);
            float q = ssq[r];
            q = fmaf(c[r].x, c[r].x, q);
            q = fmaf(c[r].y, c[r].y, q);
            q = fmaf(c[r].z, c[r].z, q);
            q = fmaf(c[r].w, c[r].w, q);
            ssq[r] = q;
        }
        const float4* wrow = &sW[(s * 32 + lane) * WPAD];
#pragma unroll
        for (int n = 0; n < NL; n++) {
            float4 w = wrow[n];                 // one LDS serves 8 rows
#pragma unroll
            for (int r = 0; r < R; r++) {
                float d = dots[r][n];
                d = fmaf(c[r].x, w.x, d);
                d = fmaf(c[r].y, w.y, d);
                d = fmaf(c[r].z, w.z, d);
                d = fmaf(c[r].w, w.w, d);
                dots[r][n] = d;
            }
        }
        __syncwarp();   // all lanes done reading buffer (s&1) before refill
        if (s + 2 < NSTAGE) {
            issue_stage(s + 2);
        } else {
            asm volatile("cp.async.commit_group;" ::: "memory");  // uniform count
        }
    }

    // ---------------- reduce + stash stats ----------------
#pragma unroll
    for (int r = 0; r < R; r++) {
        float s = sum[r];
        float q = ssq[r];
        float dv[NL];
#pragma unroll
        for (int n = 0; n < NL; n++) dv[n] = dots[r][n];
#pragma unroll
        for (int o = 16; o; o >>= 1) {
            s += __shfl_xor_sync(0xffffffffu, s, o);
            q += __shfl_xor_sync(0xffffffffu, q, o);
#pragma unroll
            for (int n = 0; n < NL; n++)
                dv[n] += __shfl_xor_sync(0xffffffffu, dv[n], o);
        }
        if (lane == 0) {
            sStats[wid * R + r][0] = s;
            sStats[wid * R + r][1] = q;
#pragma unroll
            for (int n = 0; n < NL; n++) sStats[wid * R + r][2 + n] = dv[n];
        }
    }
    __syncthreads();

    // ---------------- tail: 256 threads, 64 rows x 8 levels (2 each) --------
    {
        int rr = tid >> 2;                 // row slot 0..63
        int n0 = (tid & 3) << 1;           // levels n0, n0+1
        int orow = rowBase + rr;
        float s  = sStats[rr][0];
        float q  = sStats[rr][1];
        float mu   = s * (1.0f / 1024.0f);
        float var  = fmaf(-mu, mu, q * (1.0f / 1024.0f));
        float rstd = __frcp_rn(__fsqrt_rn(var + 1e-5f));
#pragma unroll
        for (int j = 0; j < 2; j++) {
            int n = n0 + j;
            float dv = sStats[rr][2 + n];
            float lg = fmaf(rstd, fmaf(-mu, sSB[n], dv), sSB[8 + n]);
            out[(size_t)orow * NL + n] = tanh4_round(lg);
        }
    }
}

extern "C" void kernel_launch(void* const* d_in, const int* in_sizes, int n_in,
                              void* d_out, int out_size)
{
    const float* x     = (const float*)d_in[0];  // [8,8192,1024]
    const float* gamma = (const float*)d_in[1];  // [1024]
    const float* beta  = (const float*)d_in[2];  // [1024]
    const float* W     = (const float*)d_in[3];  // [8,1024]
    float* out = (float*)d_out;                  // [8,8192,8]

    static int smem_set = 0;
    if (!smem_set) {
        cudaFuncSetAttribute(fsq_kernel,
                             cudaFuncAttributeMaxDynamicSharedMemorySize,
                             SMEM_TOTAL);
        smem_set = 1;
    }

    int rows = in_sizes[0] / D;
    int grid = (rows + ROWS_PB - 1) / ROWS_PB;
    fsq_kernel<<<grid, 256, SMEM_TOTAL>>>(x, gamma, beta, W, out, rows);
}

// round 15
// speedup vs baseline: 1.3273x; 1.3273x over previous
#include <cuda_runtime.h>
#include <cuda_bf16.h>
#include <cstdint>

// FSQ: q = round(4*tanh( W @ LayerNorm(x) )), folded into a single pass:
//   logit_n = rstd * (dot(x, gamma*W_n) - mu * s_n) + b_n
// R15: R=6 rows/warp, scalar dots+stats (R=8 spilled at 128 regs; R=6 bill
// ~105). One W-LDS serves 6 rows -> l1tex/row 2.33 vs 3.0 (R4 geometry).
// Warp-private cp.async NBUF=2 pipeline, no block barriers in mainloop.

typedef unsigned long long u64;

// rintf(4*tanh(x)), fast-math-proof (fmaf/rcp.rn/sqrt.rn only).
__device__ __forceinline__ float tanh4_round(float x) {
    float ax = fabsf(x);
    float r;
    if (ax >= 1.5f) {
        r = 4.0f;   // 4*tanh(1.5)=3.6206 -> 4; monotone beyond
    } else {
        const float T2L = 2.8853900817779268f;   // 2*log2(e)
        float t = ax * T2L;
        float k = rintf(t);
        float f = t - k;
        float y = f * 0.6931471805599453f;
        float p = 1.9841269841e-4f;
        p = fmaf(p, y, 1.3888888888e-3f);
        p = fmaf(p, y, 8.3333333333e-3f);
        p = fmaf(p, y, 4.1666666667e-2f);
        p = fmaf(p, y, 1.6666666667e-1f);
        p = fmaf(p, y, 0.5f);
        p = fmaf(p, y, 1.0f);
        p = fmaf(p, y, 1.0f);
        float scale = __int_as_float(((int)k + 127) << 23);
        float e = p * scale;                     // exp(2*ax)
        float th = (e - 1.0f) * __frcp_rn(e + 1.0f);
        r = rintf(4.0f * th);
    }
    return copysignf(r, x);
}

static const int D       = 1024;
static const int F4      = 256;   // 16B chunks per row
static const int NL      = 8;
static const int WPAD    = 9;     // float4 entries per chunk (8 + 1 pad)
static const int R       = 6;     // rows per warp
static const int ROWS_PB = 48;    // 8 warps * 6 rows
static const int NSTAGE  = 8;     // stages of 32 chunks (512B/row)
static const int NBUF    = 2;     // double buffer (warp-private)

// dynamic smem layout (bytes)
static const int SW_BYTES = F4 * WPAD * 16;             // 36864
static const int SX_BYTES = 8 * NBUF * R * 32 * 16;     // 49152 (8 warps)
static const int ST_BYTES = ROWS_PB * 12 * 4;           // 2304
static const int SR_BYTES = 8 * 16 * 4;                 // 512
static const int SMEM_TOTAL = SW_BYTES + SX_BYTES + ST_BYTES + SR_BYTES + 64;

__global__ void __launch_bounds__(256, 2)
fsq_kernel(const float* __restrict__ x, const float* __restrict__ gamma,
           const float* __restrict__ beta, const float* __restrict__ W,
           float* __restrict__ out, int rows)
{
    extern __shared__ unsigned char smem_raw[];
    float4* sW = (float4*)smem_raw;                                // [F4*WPAD]
    float4* sX = (float4*)(smem_raw + SW_BYTES);                   // [8][NBUF][6][32]
    float (*sStats)[12] = (float(*)[12])(smem_raw + SW_BYTES + SX_BYTES);
    float (*sRed)[16]   = (float(*)[16])(smem_raw + SW_BYTES + SX_BYTES + ST_BYTES);
    float* sSB          = (float*)(smem_raw + SW_BYTES + SX_BYTES + ST_BYTES + SR_BYTES);

    const int tid  = threadIdx.x;
    const int lane = tid & 31;
    const int wid  = tid >> 5;

    int rowBase = blockIdx.x * ROWS_PB;
    if (rowBase > rows - ROWS_PB) rowBase = rows - ROWS_PB;  // overlap idempotent
    if (rowBase < 0) rowBase = 0;

    // this warp's private region: NBUF stages x 6 rows x 32 chunks
    const uint32_t sx_u32 = (uint32_t)__cvta_generic_to_shared(sX)
                          + (uint32_t)wid * (NBUF * R * 32 * 16);
    const float4* x4 = (const float4*)x;
    const int myRow = rowBase + wid * R;

    // ---- warp-private cp.async stage issuer: stage s -> buffer (s & 1) ----
    auto issue_stage = [&](int s) {
        uint32_t dbase = sx_u32 + (uint32_t)(s & (NBUF - 1)) * (R * 32 * 16);
#pragma unroll
        for (int r = 0; r < R; r++) {
            const float4* src = x4 + (size_t)(myRow + r) * F4 + s * 32 + lane;
            uint32_t dst = dbase + (uint32_t)(r * 32 + lane) * 16;
            asm volatile("cp.async.cg.shared.global [%0], [%1], 16;"
                         :: "r"(dst), "l"(src) : "memory");
        }
        asm volatile("cp.async.commit_group;" ::: "memory");
    };

    // prologue: both buffers in flight before anything else
    issue_stage(0);
    issue_stage(1);

    // ---------------- prep: W' = gamma*W into smem; s_n, b_n ----------------
    float sP[NL], bP[NL];
#pragma unroll
    for (int n = 0; n < NL; n++) { sP[n] = 0.0f; bP[n] = 0.0f; }
    {
        const float4* g4 = (const float4*)gamma;  // [256]
        const float4* e4 = (const float4*)beta;
        const float4* W4 = (const float4*)W;      // [8][256]
        int i = tid;                              // 256 threads = 256 chunks
        float4 g = g4[i];
        float4 b = e4[i];
#pragma unroll
        for (int n = 0; n < NL; n++) {
            float4 w = W4[n * F4 + i];
            float4 p;
            p.x = g.x * w.x; p.y = g.y * w.y; p.z = g.z * w.z; p.w = g.w * w.w;
            sW[i * WPAD + n] = p;
            sP[n] += (p.x + p.y) + (p.z + p.w);
            bP[n] += (b.x * w.x + b.y * w.y) + (b.z * w.z + b.w * w.w);
        }
    }
#pragma unroll
    for (int o = 16; o; o >>= 1) {
#pragma unroll
        for (int n = 0; n < NL; n++) {
            sP[n] += __shfl_xor_sync(0xffffffffu, sP[n], o);
            bP[n] += __shfl_xor_sync(0xffffffffu, bP[n], o);
        }
    }
    if (lane == 0) {
#pragma unroll
        for (int n = 0; n < NL; n++) {
            sRed[wid][n]     = sP[n];
            sRed[wid][8 + n] = bP[n];
        }
    }
    __syncthreads();
    if (tid < 16) {
        float v = 0.0f;
#pragma unroll
        for (int w = 0; w < 8; w++) v += sRed[w][tid];
        sSB[tid] = v;
    }
    __syncthreads();   // sW/sSB visible; mainloop has no block barriers

    // ---------------- main: warp-private staged pipeline ----------------
    float dots[R][NL];                 // scalar accumulators (48 regs)
    float sum[R], ssq[R];              // scalar stats (12 regs)
#pragma unroll
    for (int r = 0; r < R; r++) {
        sum[r] = 0.0f; ssq[r] = 0.0f;
#pragma unroll
        for (int n = 0; n < NL; n++) dots[r][n] = 0.0f;
    }

#pragma unroll
    for (int s = 0; s < NSTAGE; s++) {
        // this warp's stage s landed (1 newer group may be pending)
        asm volatile("cp.async.wait_group 1;" ::: "memory");
        __syncwarp();

        // consume stage s: all 6 rows resident, W streamed per level
        const float4* xbuf = (const float4*)(smem_raw + SW_BYTES)
            + (size_t)wid * (NBUF * R * 32)
            + (s & (NBUF - 1)) * (R * 32) + lane;
        float4 c[R];
#pragma unroll
        for (int r = 0; r < R; r++) c[r] = xbuf[r * 32];

#pragma unroll
        for (int r = 0; r < R; r++) {
            sum[r] += (c[r].x + c[r].y) + (c[r].z + c[r].w);
            float q = ssq[r];
            q = fmaf(c[r].x, c[r].x, q);
            q = fmaf(c[r].y, c[r].y, q);
            q = fmaf(c[r].z, c[r].z, q);
            q = fmaf(c[r].w, c[r].w, q);
            ssq[r] = q;
        }
        const float4* wrow = &sW[(s * 32 + lane) * WPAD];
#pragma unroll
        for (int n = 0; n < NL; n++) {
            float4 w = wrow[n];                 // one LDS serves 6 rows
#pragma unroll
            for (int r = 0; r < R; r++) {
                float d = dots[r][n];
                d = fmaf(c[r].x, w.x, d);
                d = fmaf(c[r].y, w.y, d);
                d = fmaf(c[r].z, w.z, d);
                d = fmaf(c[r].w, w.w, d);
                dots[r][n] = d;
            }
        }
        __syncwarp();   // all lanes done reading buffer (s&1) before refill
        if (s + 2 < NSTAGE) {
            issue_stage(s + 2);
        } else {
            asm volatile("cp.async.commit_group;" ::: "memory");  // uniform count
        }
    }

    // ---------------- reduce + stash stats ----------------
#pragma unroll
    for (int r = 0; r < R; r++) {
        float s = sum[r];
        float q = ssq[r];
        float dv[NL];
#pragma unroll
        for (int n = 0; n < NL; n++) dv[n] = dots[r][n];
#pragma unroll
        for (int o = 16; o; o >>= 1) {
            s += __shfl_xor_sync(0xffffffffu, s, o);
            q += __shfl_xor_sync(0xffffffffu, q, o);
#pragma unroll
            for (int n = 0; n < NL; n++)
                dv[n] += __shfl_xor_sync(0xffffffffu, dv[n], o);
        }
        if (lane == 0) {
            sStats[wid * R + r][0] = s;
            sStats[wid * R + r][1] = q;
#pragma unroll
            for (int n = 0; n < NL; n++) sStats[wid * R + r][2 + n] = dv[n];
        }
    }
    __syncthreads();

    // ---------------- tail: 192 threads, 48 rows x 8 levels (2 each) --------
    if (tid < ROWS_PB * 4) {
        int rr = tid >> 2;                 // row slot 0..47
        int n0 = (tid & 3) << 1;           // levels n0, n0+1
        int orow = rowBase + rr;
        float s  = sStats[rr][0];
        float q  = sStats[rr][1];
        float mu   = s * (1.0f / 1024.0f);
        float var  = fmaf(-mu, mu, q * (1.0f / 1024.0f));
        float rstd = __frcp_rn(__fsqrt_rn(var + 1e-5f));
#pragma unroll
        for (int j = 0; j < 2; j++) {
            int n = n0 + j;
            float dv = sStats[rr][2 + n];
            float lg = fmaf(rstd, fmaf(-mu, sSB[n], dv), sSB[8 + n]);
            out[(size_t)orow * NL + n] = tanh4_round(lg);
        }
    }
}

extern "C" void kernel_launch(void* const* d_in, const int* in_sizes, int n_in,
                              void* d_out, int out_size)
{
    const float* x     = (const float*)d_in[0];  // [8,8192,1024]
    const float* gamma = (const float*)d_in[1];  // [1024]
    const float* beta  = (const float*)d_in[2];  // [1024]
    const float* W     = (const float*)d_in[3];  // [8,1024]
    float* out = (float*)d_out;                  // [8,8192,8]

    static int smem_set = 0;
    if (!smem_set) {
        cudaFuncSetAttribute(fsq_kernel,
                             cudaFuncAttributeMaxDynamicSharedMemorySize,
                             SMEM_TOTAL);
        smem_set = 1;
    }

    int rows = in_sizes[0] / D;
    int grid = (rows + ROWS_PB - 1) / ROWS_PB;
    fsq_kernel<<<grid, 256, SMEM_TOTAL>>>(x, gamma, beta, W, out, rows);
}

// round 16
// speedup vs baseline: 1.3626x; 1.0266x over previous
#include <cuda_runtime.h>
#include <cuda_bf16.h>
#include <cstdint>

// FSQ: q = round(4*tanh( W @ LayerNorm(x) )), folded into a single pass:
//   logit_n = rstd * (dot(x, gamma*W_n) - mu * s_n) + b_n
// R16: R15 (R=6, scalar dots, warp-private cp.async) with a 3-deep pipeline:
// prefetch distance 2 stages (wait_group 2), so DRAM latency is covered by
// two consume periods instead of one. Buffer idx s%3 constant-folds (loop
// fully unrolled). Smem 110.8KB -> still 2 blocks/SM.

typedef unsigned long long u64;

// rintf(4*tanh(x)), fast-math-proof (fmaf/rcp.rn/sqrt.rn only).
__device__ __forceinline__ float tanh4_round(float x) {
    float ax = fabsf(x);
    float r;
    if (ax >= 1.5f) {
        r = 4.0f;   // 4*tanh(1.5)=3.6206 -> 4; monotone beyond
    } else {
        const float T2L = 2.8853900817779268f;   // 2*log2(e)
        float t = ax * T2L;
        float k = rintf(t);
        float f = t - k;
        float y = f * 0.6931471805599453f;
        float p = 1.9841269841e-4f;
        p = fmaf(p, y, 1.3888888888e-3f);
        p = fmaf(p, y, 8.3333333333e-3f);
        p = fmaf(p, y, 4.1666666667e-2f);
        p = fmaf(p, y, 1.6666666667e-1f);
        p = fmaf(p, y, 0.5f);
        p = fmaf(p, y, 1.0f);
        p = fmaf(p, y, 1.0f);
        float scale = __int_as_float(((int)k + 127) << 23);
        float e = p * scale;                     // exp(2*ax)
        float th = (e - 1.0f) * __frcp_rn(e + 1.0f);
        r = rintf(4.0f * th);
    }
    return copysignf(r, x);
}

static const int D       = 1024;
static const int F4      = 256;   // 16B chunks per row
static const int NL      = 8;
static const int WPAD    = 9;     // float4 entries per chunk (8 + 1 pad)
static const int R       = 6;     // rows per warp
static const int ROWS_PB = 48;    // 8 warps * 6 rows
static const int NSTAGE  = 8;     // stages of 32 chunks (512B/row)
static const int NBUF    = 3;     // triple buffer (warp-private, dist 2)

// dynamic smem layout (bytes)
static const int SW_BYTES = F4 * WPAD * 16;             // 36864
static const int SX_BYTES = 8 * NBUF * R * 32 * 16;     // 73728 (8 warps)
static const int ST_BYTES = ROWS_PB * 12 * 4;           // 2304
static const int SR_BYTES = 8 * 16 * 4;                 // 512
static const int SMEM_TOTAL = SW_BYTES + SX_BYTES + ST_BYTES + SR_BYTES + 64;

__global__ void __launch_bounds__(256, 2)
fsq_kernel(const float* __restrict__ x, const float* __restrict__ gamma,
           const float* __restrict__ beta, const float* __restrict__ W,
           float* __restrict__ out, int rows)
{
    extern __shared__ unsigned char smem_raw[];
    float4* sW = (float4*)smem_raw;                                // [F4*WPAD]
    float4* sX = (float4*)(smem_raw + SW_BYTES);                   // [8][NBUF][6][32]
    float (*sStats)[12] = (float(*)[12])(smem_raw + SW_BYTES + SX_BYTES);
    float (*sRed)[16]   = (float(*)[16])(smem_raw + SW_BYTES + SX_BYTES + ST_BYTES);
    float* sSB          = (float*)(smem_raw + SW_BYTES + SX_BYTES + ST_BYTES + SR_BYTES);

    const int tid  = threadIdx.x;
    const int lane = tid & 31;
    const int wid  = tid >> 5;

    int rowBase = blockIdx.x * ROWS_PB;
    if (rowBase > rows - ROWS_PB) rowBase = rows - ROWS_PB;  // overlap idempotent
    if (rowBase < 0) rowBase = 0;

    // this warp's private region: NBUF stages x 6 rows x 32 chunks
    const uint32_t sx_u32 = (uint32_t)__cvta_generic_to_shared(sX)
                          + (uint32_t)wid * (NBUF * R * 32 * 16);
    const float4* x4 = (const float4*)x;
    const int myRow = rowBase + wid * R;

    // ---- warp-private cp.async stage issuer: stage s -> buffer (s % 3) ----
    auto issue_stage = [&](int s) {
        uint32_t dbase = sx_u32 + (uint32_t)(s % NBUF) * (R * 32 * 16);
#pragma unroll
        for (int r = 0; r < R; r++) {
            const float4* src = x4 + (size_t)(myRow + r) * F4 + s * 32 + lane;
            uint32_t dst = dbase + (uint32_t)(r * 32 + lane) * 16;
            asm volatile("cp.async.cg.shared.global [%0], [%1], 16;"
                         :: "r"(dst), "l"(src) : "memory");
        }
        asm volatile("cp.async.commit_group;" ::: "memory");
    };

    // prologue: three stages in flight before anything else
    issue_stage(0);
    issue_stage(1);
    issue_stage(2);

    // ---------------- prep: W' = gamma*W into smem; s_n, b_n ----------------
    float sP[NL], bP[NL];
#pragma unroll
    for (int n = 0; n < NL; n++) { sP[n] = 0.0f; bP[n] = 0.0f; }
    {
        const float4* g4 = (const float4*)gamma;  // [256]
        const float4* e4 = (const float4*)beta;
        const float4* W4 = (const float4*)W;      // [8][256]
        int i = tid;                              // 256 threads = 256 chunks
        float4 g = g4[i];
        float4 b = e4[i];
#pragma unroll
        for (int n = 0; n < NL; n++) {
            float4 w = W4[n * F4 + i];
            float4 p;
            p.x = g.x * w.x; p.y = g.y * w.y; p.z = g.z * w.z; p.w = g.w * w.w;
            sW[i * WPAD + n] = p;
            sP[n] += (p.x + p.y) + (p.z + p.w);
            bP[n] += (b.x * w.x + b.y * w.y) + (b.z * w.z + b.w * w.w);
        }
    }
#pragma unroll
    for (int o = 16; o; o >>= 1) {
#pragma unroll
        for (int n = 0; n < NL; n++) {
            sP[n] += __shfl_xor_sync(0xffffffffu, sP[n], o);
            bP[n] += __shfl_xor_sync(0xffffffffu, bP[n], o);
        }
    }
    if (lane == 0) {
#pragma unroll
        for (int n = 0; n < NL; n++) {
            sRed[wid][n]     = sP[n];
            sRed[wid][8 + n] = bP[n];
        }
    }
    __syncthreads();
    if (tid < 16) {
        float v = 0.0f;
#pragma unroll
        for (int w = 0; w < 8; w++) v += sRed[w][tid];
        sSB[tid] = v;
    }
    __syncthreads();   // sW/sSB visible; mainloop has no block barriers

    // ---------------- main: warp-private staged pipeline ----------------
    float dots[R][NL];                 // scalar accumulators (48 regs)
    float sum[R], ssq[R];              // scalar stats (12 regs)
#pragma unroll
    for (int r = 0; r < R; r++) {
        sum[r] = 0.0f; ssq[r] = 0.0f;
#pragma unroll
        for (int n = 0; n < NL; n++) dots[r][n] = 0.0f;
    }

#pragma unroll
    for (int s = 0; s < NSTAGE; s++) {
        // this warp's stage s landed (2 newer groups may be pending)
        asm volatile("cp.async.wait_group 2;" ::: "memory");
        __syncwarp();

        // consume stage s: all 6 rows resident, W streamed per level
        const float4* xbuf = (const float4*)(smem_raw + SW_BYTES)
            + (size_t)wid * (NBUF * R * 32)
            + (s % NBUF) * (R * 32) + lane;
        float4 c[R];
#pragma unroll
        for (int r = 0; r < R; r++) c[r] = xbuf[r * 32];

#pragma unroll
        for (int r = 0; r < R; r++) {
            sum[r] += (c[r].x + c[r].y) + (c[r].z + c[r].w);
            float q = ssq[r];
            q = fmaf(c[r].x, c[r].x, q);
            q = fmaf(c[r].y, c[r].y, q);
            q = fmaf(c[r].z, c[r].z, q);
            q = fmaf(c[r].w, c[r].w, q);
            ssq[r] = q;
        }
        const float4* wrow = &sW[(s * 32 + lane) * WPAD];
#pragma unroll
        for (int n = 0; n < NL; n++) {
            float4 w = wrow[n];                 // one LDS serves 6 rows
#pragma unroll
            for (int r = 0; r < R; r++) {
                float d = dots[r][n];
                d = fmaf(c[r].x, w.x, d);
                d = fmaf(c[r].y, w.y, d);
                d = fmaf(c[r].z, w.z, d);
                d = fmaf(c[r].w, w.w, d);
                dots[r][n] = d;
            }
        }
        __syncwarp();   // all lanes done reading buffer (s%3) before refill
        if (s + 3 < NSTAGE) {
            issue_stage(s + 3);
        } else {
            asm volatile("cp.async.commit_group;" ::: "memory");  // uniform count
        }
    }

    // ---------------- reduce + stash stats ----------------
#pragma unroll
    for (int r = 0; r < R; r++) {
        float s = sum[r];
        float q = ssq[r];
        float dv[NL];
#pragma unroll
        for (int n = 0; n < NL; n++) dv[n] = dots[r][n];
#pragma unroll
        for (int o = 16; o; o >>= 1) {
            s += __shfl_xor_sync(0xffffffffu, s, o);
            q += __shfl_xor_sync(0xffffffffu, q, o);
#pragma unroll
            for (int n = 0; n < NL; n++)
                dv[n] += __shfl_xor_sync(0xffffffffu, dv[n], o);
        }
        if (lane == 0) {
            sStats[wid * R + r][0] = s;
            sStats[wid * R + r][1] = q;
#pragma unroll
            for (int n = 0; n < NL; n++) sStats[wid * R + r][2 + n] = dv[n];
        }
    }
    __syncthreads();

    // ---------------- tail: 192 threads, 48 rows x 8 levels (2 each) --------
    if (tid < ROWS_PB * 4) {
        int rr = tid >> 2;                 // row slot 0..47
        int n0 = (tid & 3) << 1;           // levels n0, n0+1
        int orow = rowBase + rr;
        float s  = sStats[rr][0];
        float q  = sStats[rr][1];
        float mu   = s * (1.0f / 1024.0f);
        float var  = fmaf(-mu, mu, q * (1.0f / 1024.0f));
        float rstd = __frcp_rn(__fsqrt_rn(var + 1e-5f));
#pragma unroll
        for (int j = 0; j < 2; j++) {
            int n = n0 + j;
            float dv = sStats[rr][2 + n];
            float lg = fmaf(rstd, fmaf(-mu, sSB[n], dv), sSB[8 + n]);
            out[(size_t)orow * NL + n] = tanh4_round(lg);
        }
    }
}

extern "C" void kernel_launch(void* const* d_in, const int* in_sizes, int n_in,
                              void* d_out, int out_size)
{
    const float* x     = (const float*)d_in[0];  // [8,8192,1024]
    const float* gamma = (const float*)d_in[1];  // [1024]
    const float* beta  = (const float*)d_in[2];  // [1024]
    const float* W     = (const float*)d_in[3];  // [8,1024]
    float* out = (float*)d_out;                  // [8,8192,8]

    static int smem_set = 0;
    if (!smem_set) {
        cudaFuncSetAttribute(fsq_kernel,
                             cudaFuncAttributeMaxDynamicSharedMemorySize,
                             SMEM_TOTAL);
        smem_set = 1;
    }

    int rows = in_sizes[0] / D;
    int grid = (rows + ROWS_PB - 1) / ROWS_PB;
    fsq_kernel<<<grid, 256, SMEM_TOTAL>>>(x, gamma, beta, W, out, rows);
}